// round 14
// baseline (speedup 1.0000x reference)
#include <cuda_runtime.h>
#include <cuda_fp16.h>
#include <cstdint>

#define N_NODES 100000
#define N_EDGES 1600000
#define D 128
#define ELL_W 64
#define SPLIT_M 50048   // 391 gemm blocks * 128

// ---------------- scratch (device globals; no allocation allowed) ----------------
__device__ __align__(256) unsigned long long g_deg64[N_NODES]; // packed (cnt<<40 | wsum q20)
__device__ __align__(256) float  g_dis[N_NODES];              // rsqrt(weighted deg)
__device__ __align__(256) int    g_cnt[N_NODES];              // in-degree (clamped)
__device__ __align__(256) int2   g_ell[(size_t)N_NODES * ELL_W]; // ELL (src, w-bits)
__device__ __align__(256) __half g_h16[(size_t)N_NODES * D];  // GEMM output (fp16)
__device__ __align__(256) float  g_x1[(size_t)N_NODES * D];   // layer-1 activated out
__device__ int g_idx64;                                       // edge_index dtype flag

// ---------------- helpers ----------------
__device__ __forceinline__ int clampN(int v) {
    v = v < 0 ? 0 : v;
    return v >= N_NODES ? N_NODES - 1 : v;
}

__device__ __forceinline__ int eidx(const void* ei, int is64, size_t pos) {
    if (is64) return clampN((int)((const long long*)ei)[pos]);
    return clampN(((const int*)ei)[pos]);
}

__device__ __forceinline__ uint32_t smem_u32(const void* p) {
    return (uint32_t)__cvta_generic_to_shared(p);
}

__device__ __forceinline__ void ldm_x4(uint32_t* r, uint32_t addr) {
    asm volatile("ldmatrix.sync.aligned.m8n8.x4.shared.b16 {%0,%1,%2,%3}, [%4];"
                 : "=r"(r[0]), "=r"(r[1]), "=r"(r[2]), "=r"(r[3]) : "r"(addr));
}

__device__ __forceinline__ void ldm_x4_t(uint32_t* r, uint32_t addr) {
    asm volatile("ldmatrix.sync.aligned.m8n8.x4.trans.shared.b16 {%0,%1,%2,%3}, [%4];"
                 : "=r"(r[0]), "=r"(r[1]), "=r"(r[2]), "=r"(r[3]) : "r"(addr));
}

__device__ __forceinline__ void mma_f16(float* c, const uint32_t* a, uint32_t b0, uint32_t b1) {
    asm volatile(
        "mma.sync.aligned.m16n8k16.row.col.f32.f16.f16.f32 "
        "{%0,%1,%2,%3}, {%4,%5,%6,%7}, {%8,%9}, {%0,%1,%2,%3};"
        : "+f"(c[0]), "+f"(c[1]), "+f"(c[2]), "+f"(c[3])
        : "r"(a[0]), "r"(a[1]), "r"(a[2]), "r"(a[3]), "r"(b0), "r"(b1));
}

__device__ __forceinline__ float4 ld_h4(const __half* p) {
    uint2 raw = *(const uint2*)p;
    __half2 p0 = *reinterpret_cast<__half2*>(&raw.x);
    __half2 p1 = *reinterpret_cast<__half2*>(&raw.y);
    float2 f0 = __half22float2(p0);
    float2 f1 = __half22float2(p1);
    return make_float4(f0.x, f0.y, f1.x, f1.y);
}

// ---------------- prep (+ dtype probe) ----------------
__global__ void k_prep(const int* __restrict__ ei32) {
    int i = blockIdx.x * 256 + threadIdx.x;
    if (i < N_NODES) g_deg64[i] = 0ULL;
    if (i == 0) {
        int odd_or = 0;
#pragma unroll
        for (int k = 1; k < 128; k += 2) odd_or |= ei32[k];
        g_idx64 = (odd_or == 0) ? 1 : 0;
    }
}

// ---------------- single-pass ELL build: atomic return value = slot ----------------
__global__ void k_fill_ell(const void* __restrict__ ei, const float* __restrict__ w) {
    int e = blockIdx.x * 256 + threadIdx.x;
    if (e < N_EDGES) {
        int is64 = g_idx64;
        int s = eidx(ei, is64, e);
        int d = eidx(ei, is64, (size_t)N_EDGES + e);
        float we = w[e];
        unsigned int q = __float2uint_rn(we * 1048576.0f);   // q20 fixed point
        unsigned long long old =
            atomicAdd(&g_deg64[d], (1ULL << 40) | (unsigned long long)q);
        int slot = (int)(old >> 40);
        if (slot < ELL_W)
            g_ell[(size_t)d * ELL_W + slot] = make_int2(s, __float_as_int(we));
    }
}

// ---------------- finalize: dis = rsqrt(wsum+1), cnt ----------------
__global__ void k_dis() {
    int i = blockIdx.x * 256 + threadIdx.x;
    if (i < N_NODES) {
        unsigned long long p = g_deg64[i];
        int c = (int)(p >> 40);
        float wsum = (float)(p & ((1ULL << 40) - 1)) * (1.0f / 1048576.0f);
        g_dis[i] = rsqrtf(wsum + 1.0f);   // +1 self-loop
        g_cnt[i] = c < ELL_W ? c : ELL_W;
    }
}

// ---------------- FP16 tensor-core GEMM, double-buffered: H16 = A @ W ----------
// m_off: starting row (for chunked pipelining).
__global__ void __launch_bounds__(256, 2)
k_gemm(const float* __restrict__ Aext, int a_sel, const float* __restrict__ W, int m_off)
{
    __shared__ __half As[2][128][24];   // [m][k], 24-half stride: ldmatrix conflict-free
    __shared__ __half Bs[2][16][136];   // [k][n], 136-half stride: ldmatrix conflict-free

    const float* A = (a_sel == 0) ? Aext : g_x1;

    const int tid  = threadIdx.x;
    const int m0   = m_off + blockIdx.x * 128;
    const int wid  = tid >> 5, lane = tid & 31;
    const int wm   = wid >> 1, wn = wid & 1;      // warp grid 4x2
    const int gid  = lane >> 2, tig = lane & 3;   // mma accum coords
    const int li   = lane & 7,  lsel = lane >> 3; // ldmatrix coords

    float c[2][8][4];
#pragma unroll
    for (int mt = 0; mt < 2; mt++)
#pragma unroll
        for (int nt = 0; nt < 8; nt++)
#pragma unroll
            for (int q = 0; q < 4; q++) c[mt][nt][q] = 0.0f;

    float4 ra[2], rb[2];

    auto load_chunk = [&](int ch) {
#pragma unroll
        for (int it = 0; it < 2; it++) {
            int idx = tid + it * 256;
            int row = idx >> 2, c4 = idx & 3;
            int gm = m0 + row;
            float4 v = make_float4(0.f, 0.f, 0.f, 0.f);
            if (gm < N_NODES)
                v = *(const float4*)(A + (size_t)gm * D + ch * 16 + c4 * 4);
            ra[it] = v;
        }
#pragma unroll
        for (int it = 0; it < 2; it++) {
            int idx = tid + it * 256;
            int row = idx >> 5, c4 = idx & 31;
            rb[it] = *(const float4*)(W + (size_t)(ch * 16 + row) * D + c4 * 4);
        }
    };

    auto store_chunk = [&](int buf) {
#pragma unroll
        for (int it = 0; it < 2; it++) {
            int idx = tid + it * 256;
            int row = idx >> 2, c4 = idx & 3;
            __half2 h01 = __floats2half2_rn(ra[it].x, ra[it].y);
            __half2 h23 = __floats2half2_rn(ra[it].z, ra[it].w);
            uint2 u = make_uint2(*(uint32_t*)&h01, *(uint32_t*)&h23);
            *(uint2*)&As[buf][row][c4 * 4] = u;
        }
#pragma unroll
        for (int it = 0; it < 2; it++) {
            int idx = tid + it * 256;
            int row = idx >> 5, c4 = idx & 31;
            __half2 h01 = __floats2half2_rn(rb[it].x, rb[it].y);
            __half2 h23 = __floats2half2_rn(rb[it].z, rb[it].w);
            uint2 u = make_uint2(*(uint32_t*)&h01, *(uint32_t*)&h23);
            *(uint2*)&Bs[buf][row][c4 * 4] = u;
        }
    };

    load_chunk(0);
    store_chunk(0);
    __syncthreads();

    const int NCH = D / 16;  // 8
#pragma unroll
    for (int ch = 0; ch < NCH; ch++) {
        int buf = ch & 1;
        if (ch + 1 < NCH) load_chunk(ch + 1);

        uint32_t af[2][4];
#pragma unroll
        for (int mt = 0; mt < 2; mt++) {
            int row = wm * 32 + mt * 16 + (lsel & 1) * 8 + li;
            int col = (lsel >> 1) * 8;
            ldm_x4(af[mt], smem_u32(&As[buf][row][col]));
        }
        uint32_t bf[4][4];
#pragma unroll
        for (int np = 0; np < 4; np++) {
            int row = (lsel & 1) * 8 + li;
            int col = wn * 64 + np * 16 + (lsel >> 1) * 8;
            ldm_x4_t(bf[np], smem_u32(&Bs[buf][row][col]));
        }
#pragma unroll
        for (int mt = 0; mt < 2; mt++)
#pragma unroll
            for (int nt = 0; nt < 8; nt++)
                mma_f16(c[mt][nt], af[mt], bf[nt >> 1][(nt & 1) * 2], bf[nt >> 1][(nt & 1) * 2 + 1]);

        if (ch + 1 < NCH) {
            store_chunk(buf ^ 1);
            __syncthreads();
        }
    }

#pragma unroll
    for (int mt = 0; mt < 2; mt++) {
        int r0 = m0 + wm * 32 + mt * 16 + gid;
#pragma unroll
        for (int nt = 0; nt < 8; nt++) {
            int col = wn * 64 + nt * 8 + tig * 2;
            if (r0 < N_NODES)
                *(__half2*)(g_h16 + (size_t)r0 * D + col) =
                    __floats2half2_rn(c[mt][nt][0], c[mt][nt][1]);
            if (r0 + 8 < N_NODES)
                *(__half2*)(g_h16 + (size_t)(r0 + 8) * D + col) =
                    __floats2half2_rn(c[mt][nt][2], c[mt][nt][3]);
        }
    }
}

// ---------------- gather: out[d] = prelu((h[d]*dis_d + Sum w*dis_s*h[s])*dis_d + b, a)
// One warp per destination node; ELL rows; norm factored (dis_d applied once).
__global__ void __launch_bounds__(256)
k_gather(int agg_sel, float* __restrict__ out_ext,
         const float* __restrict__ bias, const float* __restrict__ alpha, int n_off)
{
    int node = n_off + blockIdx.x * 8 + (threadIdx.x >> 5);
    if (node >= N_NODES) return;
    int lane = threadIdx.x & 31;

    float* AGG = (agg_sel == 1) ? g_x1 : out_ext;

    int cnt = g_cnt[node];
    float dn = g_dis[node];
    const int2* erow = g_ell + (size_t)node * ELL_W;

    float4 hv = ld_h4(g_h16 + (size_t)node * D + lane * 4);
    float4 acc = make_float4(hv.x * dn, hv.y * dn, hv.z * dn, hv.w * dn);

    int j = 0;
    for (; j + 3 < cnt; j += 4) {
        int2 e0 = erow[j],     e1 = erow[j + 1];
        int2 e2 = erow[j + 2], e3 = erow[j + 3];
        float4 h0 = ld_h4(g_h16 + (size_t)e0.x * D + lane * 4);
        float4 h1 = ld_h4(g_h16 + (size_t)e1.x * D + lane * 4);
        float4 h2 = ld_h4(g_h16 + (size_t)e2.x * D + lane * 4);
        float4 h3 = ld_h4(g_h16 + (size_t)e3.x * D + lane * 4);
        float v0 = __int_as_float(e0.y) * g_dis[e0.x];
        float v1 = __int_as_float(e1.y) * g_dis[e1.x];
        float v2 = __int_as_float(e2.y) * g_dis[e2.x];
        float v3 = __int_as_float(e3.y) * g_dis[e3.x];
        acc.x += h0.x * v0; acc.y += h0.y * v0; acc.z += h0.z * v0; acc.w += h0.w * v0;
        acc.x += h1.x * v1; acc.y += h1.y * v1; acc.z += h1.z * v1; acc.w += h1.w * v1;
        acc.x += h2.x * v2; acc.y += h2.y * v2; acc.z += h2.z * v2; acc.w += h2.w * v2;
        acc.x += h3.x * v3; acc.y += h3.y * v3; acc.z += h3.z * v3; acc.w += h3.w * v3;
    }
    for (; j < cnt; j++) {
        int2 e0 = erow[j];
        float v0 = __int_as_float(e0.y) * g_dis[e0.x];
        float4 h0 = ld_h4(g_h16 + (size_t)e0.x * D + lane * 4);
        acc.x += h0.x * v0; acc.y += h0.y * v0; acc.z += h0.z * v0; acc.w += h0.w * v0;
    }

    acc.x *= dn; acc.y *= dn; acc.z *= dn; acc.w *= dn;

    if (bias) {
        int col = lane * 4;
        acc.x += bias[col + 0]; acc.x = acc.x >= 0.f ? acc.x : alpha[col + 0] * acc.x;
        acc.y += bias[col + 1]; acc.y = acc.y >= 0.f ? acc.y : alpha[col + 1] * acc.y;
        acc.z += bias[col + 2]; acc.z = acc.z >= 0.f ? acc.z : alpha[col + 2] * acc.z;
        acc.w += bias[col + 3]; acc.w = acc.w >= 0.f ? acc.w : alpha[col + 3] * acc.w;
    }
    *(float4*)(AGG + (size_t)node * D + lane * 4) = acc;
}

// ---------------- launch: gemm1 || ELL build ; gather1/gemm2 chunk pipeline -------
extern "C" void kernel_launch(void* const* d_in, const int* in_sizes, int n_in,
                              void* d_out, int out_size)
{
    const float* features = (const float*)d_in[0];
    const void*  ei       = d_in[1];
    const float* ew       = (const float*)d_in[2];
    const float* W1       = (const float*)d_in[3];
    const float* b1       = (const float*)d_in[4];
    const float* a1       = (const float*)d_in[5];
    const float* W2       = (const float*)d_in[6];
    const float* b2       = (const float*)d_in[7];
    const float* a2       = (const float*)d_in[8];
    float* out = (float*)d_out;

    const int nodeBlocks = (N_NODES + 255) / 256;            // 391
    const int edgeBlocks = (N_EDGES + 255) / 256;            // 6250
    const int gemmBlocks = (N_NODES + 127) / 128;            // 782
    const int gemmLo     = SPLIT_M / 128;                    // 391
    const int gemmHi     = gemmBlocks - gemmLo;              // 391
    const int gathLo     = SPLIT_M / 8;                      // 6256
    const int gathHi     = (N_NODES - SPLIT_M + 7) / 8;      // 6244
    const int gathBlocks = (N_NODES + 7) / 8;                // 12500

    cudaStream_t s2;
    cudaEvent_t ev_fork, e_g1, e_lo, e_hi, e_j;
    cudaStreamCreateWithFlags(&s2, cudaStreamNonBlocking);
    cudaEventCreateWithFlags(&ev_fork, cudaEventDisableTiming);
    cudaEventCreateWithFlags(&e_g1, cudaEventDisableTiming);
    cudaEventCreateWithFlags(&e_lo, cudaEventDisableTiming);
    cudaEventCreateWithFlags(&e_hi, cudaEventDisableTiming);
    cudaEventCreateWithFlags(&e_j, cudaEventDisableTiming);

    // fork: GEMM-1 (independent of graph build) on s2
    cudaEventRecord(ev_fork, 0);
    cudaStreamWaitEvent(s2, ev_fork, 0);
    k_gemm<<<gemmBlocks, 256, 0, s2>>>(features, 0, W1, 0);
    cudaEventRecord(e_g1, s2);

    // main: single-pass ELL build
    k_prep<<<nodeBlocks, 256>>>((const int*)ei);
    k_fill_ell<<<edgeBlocks, 256>>>(ei, ew);
    k_dis<<<nodeBlocks, 256>>>();

    // gather-1 chunked; gemm-2 chunks pipeline on s2
    cudaStreamWaitEvent(0, e_g1, 0);
    k_gather<<<gathLo, 256>>>(1, out, b1, a1, 0);
    cudaEventRecord(e_lo, 0);
    k_gather<<<gathHi, 256>>>(1, out, b1, a1, SPLIT_M);
    cudaEventRecord(e_hi, 0);

    cudaStreamWaitEvent(s2, e_lo, 0);
    k_gemm<<<gemmLo, 256, 0, s2>>>(features, 1, W2, 0);
    cudaStreamWaitEvent(s2, e_hi, 0);
    k_gemm<<<gemmHi, 256, 0, s2>>>(features, 1, W2, SPLIT_M);
    cudaEventRecord(e_j, s2);

    cudaStreamWaitEvent(0, e_j, 0);
    k_gather<<<gathBlocks, 256>>>(2, out, b2, a2, 0);

    cudaEventDestroy(ev_fork);
    cudaEventDestroy(e_g1);
    cudaEventDestroy(e_lo);
    cudaEventDestroy(e_hi);
    cudaEventDestroy(e_j);
    cudaStreamDestroy(s2);
}

// round 15
// speedup vs baseline: 1.0774x; 1.0774x over previous
#include <cuda_runtime.h>
#include <cuda_fp16.h>
#include <cstdint>

#define N_NODES 100000
#define N_EDGES 1600000
#define D 128
#define SCAN_B 1024
#define N_SCAN_BLOCKS ((N_NODES + SCAN_B - 1) / SCAN_B)   // 98
#define SPLIT_M 50048   // 391 gemm blocks * 128

// ---------------- scratch (device globals; no allocation allowed) ----------------
__device__ __align__(256) unsigned long long g_deg64[N_NODES]; // packed (cnt<<40 | wsum q20)
__device__ __align__(256) float  g_dis[N_NODES];              // rsqrt(deg)
__device__ __align__(256) int    g_cnt[N_NODES];              // in-degree (edges only)
__device__ __align__(256) int    g_rowstart[N_NODES];         // CSR row offsets
__device__ __align__(256) int    g_cursor[N_NODES];           // fill cursors (pre-offset)
__device__ __align__(256) int2   g_edge[N_EDGES];             // CSR (src, norm-bits)
__device__ __align__(256) __half g_h16[(size_t)N_NODES * D];  // GEMM output (fp16)
__device__ __align__(256) float  g_x1[(size_t)N_NODES * D];   // layer-1 activated out
__device__ int g_idx64;                                       // edge_index dtype flag
__device__ int g_total;                                       // scan offset counter

// ---------------- helpers ----------------
__device__ __forceinline__ int clampN(int v) {
    v = v < 0 ? 0 : v;
    return v >= N_NODES ? N_NODES - 1 : v;
}

__device__ __forceinline__ int eidx(const void* ei, int is64, size_t pos) {
    if (is64) return clampN((int)((const long long*)ei)[pos]);
    return clampN(((const int*)ei)[pos]);
}

__device__ __forceinline__ uint32_t smem_u32(const void* p) {
    return (uint32_t)__cvta_generic_to_shared(p);
}

__device__ __forceinline__ void ldm_x4(uint32_t* r, uint32_t addr) {
    asm volatile("ldmatrix.sync.aligned.m8n8.x4.shared.b16 {%0,%1,%2,%3}, [%4];"
                 : "=r"(r[0]), "=r"(r[1]), "=r"(r[2]), "=r"(r[3]) : "r"(addr));
}

__device__ __forceinline__ void ldm_x4_t(uint32_t* r, uint32_t addr) {
    asm volatile("ldmatrix.sync.aligned.m8n8.x4.trans.shared.b16 {%0,%1,%2,%3}, [%4];"
                 : "=r"(r[0]), "=r"(r[1]), "=r"(r[2]), "=r"(r[3]) : "r"(addr));
}

__device__ __forceinline__ void mma_f16(float* c, const uint32_t* a, uint32_t b0, uint32_t b1) {
    asm volatile(
        "mma.sync.aligned.m16n8k16.row.col.f32.f16.f16.f32 "
        "{%0,%1,%2,%3}, {%4,%5,%6,%7}, {%8,%9}, {%0,%1,%2,%3};"
        : "+f"(c[0]), "+f"(c[1]), "+f"(c[2]), "+f"(c[3])
        : "r"(a[0]), "r"(a[1]), "r"(a[2]), "r"(a[3]), "r"(b0), "r"(b1));
}

__device__ __forceinline__ float4 ld_h4(const __half* p) {
    uint2 raw = *(const uint2*)p;
    __half2 p0 = *reinterpret_cast<__half2*>(&raw.x);
    __half2 p1 = *reinterpret_cast<__half2*>(&raw.y);
    float2 f0 = __half22float2(p0);
    float2 f1 = __half22float2(p1);
    return make_float4(f0.x, f0.y, f1.x, f1.y);
}

// ---------------- prep (+ dtype probe + scan counter reset) ----------------
__global__ void k_prep(const int* __restrict__ ei32) {
    int i = blockIdx.x * 256 + threadIdx.x;
    if (i < N_NODES) g_deg64[i] = 0ULL;
    if (i == 0) {
        g_total = 0;
        int odd_or = 0;
#pragma unroll
        for (int k = 1; k < 128; k += 2) odd_or |= ei32[k];
        g_idx64 = (odd_or == 0) ? 1 : 0;
    }
}

// ---------------- degree + count: ONE packed 64-bit atomic per edge ----------------
__global__ void k_deg_cnt(const void* __restrict__ ei, const float* __restrict__ w) {
    int e = blockIdx.x * 256 + threadIdx.x;
    if (e < N_EDGES) {
        int is64 = g_idx64;
        int d = eidx(ei, is64, (size_t)N_EDGES + e);
        unsigned int q = __float2uint_rn(w[e] * 1048576.0f);   // q20 fixed point
        atomicAdd(&g_deg64[d], (1ULL << 40) | (unsigned long long)q);
    }
}

// ---------------- single-kernel scan: local scan + atomic block base --------------
__global__ void k_scan() {
    __shared__ int sm[SCAN_B];
    __shared__ int base_sh;
    int tid = threadIdx.x;
    int i = blockIdx.x * SCAN_B + tid;
    int v = 0;
    if (i < N_NODES) {
        unsigned long long p = g_deg64[i];
        v = (int)(p >> 40);
        float wsum = (float)(p & ((1ULL << 40) - 1)) * (1.0f / 1048576.0f);
        g_dis[i] = rsqrtf(wsum + 1.0f);   // +1 self-loop
        g_cnt[i] = v;
    }
    sm[tid] = v;
    __syncthreads();
#pragma unroll
    for (int off = 1; off < SCAN_B; off <<= 1) {
        int t = (tid >= off) ? sm[tid - off] : 0;
        __syncthreads();
        sm[tid] += t;
        __syncthreads();
    }
    if (tid == SCAN_B - 1) base_sh = atomicAdd(&g_total, sm[tid]);
    __syncthreads();
    if (i < N_NODES) {
        int rs = base_sh + sm[tid] - v;
        g_rowstart[i] = rs;
        g_cursor[i] = rs;
    }
}

// ---------------- CSR fill: packed (src, norm) records ----------------
__global__ void k_fill(const void* __restrict__ ei, const float* __restrict__ w) {
    int e = blockIdx.x * 256 + threadIdx.x;
    if (e < N_EDGES) {
        int is64 = g_idx64;
        int s = eidx(ei, is64, e);
        int d = eidx(ei, is64, (size_t)N_EDGES + e);
        float nm = g_dis[s] * w[e] * g_dis[d];
        int pos = atomicAdd(&g_cursor[d], 1);
        pos = pos < 0 ? 0 : (pos >= N_EDGES ? N_EDGES - 1 : pos);
        g_edge[pos] = make_int2(s, __float_as_int(nm));
    }
}

// ---------------- FP16 tensor-core GEMM, double-buffered: H16 = A @ W ----------
__global__ void __launch_bounds__(256, 2)
k_gemm(const float* __restrict__ Aext, int a_sel, const float* __restrict__ W, int m_off)
{
    __shared__ __half As[2][128][24];   // [m][k], 24-half stride: ldmatrix conflict-free
    __shared__ __half Bs[2][16][136];   // [k][n], 136-half stride: ldmatrix conflict-free

    const float* A = (a_sel == 0) ? Aext : g_x1;

    const int tid  = threadIdx.x;
    const int m0   = m_off + blockIdx.x * 128;
    const int wid  = tid >> 5, lane = tid & 31;
    const int wm   = wid >> 1, wn = wid & 1;      // warp grid 4x2
    const int gid  = lane >> 2, tig = lane & 3;   // mma accum coords
    const int li   = lane & 7,  lsel = lane >> 3; // ldmatrix coords

    float c[2][8][4];
#pragma unroll
    for (int mt = 0; mt < 2; mt++)
#pragma unroll
        for (int nt = 0; nt < 8; nt++)
#pragma unroll
            for (int q = 0; q < 4; q++) c[mt][nt][q] = 0.0f;

    float4 ra[2], rb[2];

    auto load_chunk = [&](int ch) {
#pragma unroll
        for (int it = 0; it < 2; it++) {
            int idx = tid + it * 256;
            int row = idx >> 2, c4 = idx & 3;
            int gm = m0 + row;
            float4 v = make_float4(0.f, 0.f, 0.f, 0.f);
            if (gm < N_NODES)
                v = *(const float4*)(A + (size_t)gm * D + ch * 16 + c4 * 4);
            ra[it] = v;
        }
#pragma unroll
        for (int it = 0; it < 2; it++) {
            int idx = tid + it * 256;
            int row = idx >> 5, c4 = idx & 31;
            rb[it] = *(const float4*)(W + (size_t)(ch * 16 + row) * D + c4 * 4);
        }
    };

    auto store_chunk = [&](int buf) {
#pragma unroll
        for (int it = 0; it < 2; it++) {
            int idx = tid + it * 256;
            int row = idx >> 2, c4 = idx & 3;
            __half2 h01 = __floats2half2_rn(ra[it].x, ra[it].y);
            __half2 h23 = __floats2half2_rn(ra[it].z, ra[it].w);
            uint2 u = make_uint2(*(uint32_t*)&h01, *(uint32_t*)&h23);
            *(uint2*)&As[buf][row][c4 * 4] = u;
        }
#pragma unroll
        for (int it = 0; it < 2; it++) {
            int idx = tid + it * 256;
            int row = idx >> 5, c4 = idx & 31;
            __half2 h01 = __floats2half2_rn(rb[it].x, rb[it].y);
            __half2 h23 = __floats2half2_rn(rb[it].z, rb[it].w);
            uint2 u = make_uint2(*(uint32_t*)&h01, *(uint32_t*)&h23);
            *(uint2*)&Bs[buf][row][c4 * 4] = u;
        }
    };

    load_chunk(0);
    store_chunk(0);
    __syncthreads();

    const int NCH = D / 16;  // 8
#pragma unroll
    for (int ch = 0; ch < NCH; ch++) {
        int buf = ch & 1;
        if (ch + 1 < NCH) load_chunk(ch + 1);

        uint32_t af[2][4];
#pragma unroll
        for (int mt = 0; mt < 2; mt++) {
            int row = wm * 32 + mt * 16 + (lsel & 1) * 8 + li;
            int col = (lsel >> 1) * 8;
            ldm_x4(af[mt], smem_u32(&As[buf][row][col]));
        }
        uint32_t bf[4][4];
#pragma unroll
        for (int np = 0; np < 4; np++) {
            int row = (lsel & 1) * 8 + li;
            int col = wn * 64 + np * 16 + (lsel >> 1) * 8;
            ldm_x4_t(bf[np], smem_u32(&Bs[buf][row][col]));
        }
#pragma unroll
        for (int mt = 0; mt < 2; mt++)
#pragma unroll
            for (int nt = 0; nt < 8; nt++)
                mma_f16(c[mt][nt], af[mt], bf[nt >> 1][(nt & 1) * 2], bf[nt >> 1][(nt & 1) * 2 + 1]);

        if (ch + 1 < NCH) {
            store_chunk(buf ^ 1);
            __syncthreads();
        }
    }

#pragma unroll
    for (int mt = 0; mt < 2; mt++) {
        int r0 = m0 + wm * 32 + mt * 16 + gid;
#pragma unroll
        for (int nt = 0; nt < 8; nt++) {
            int col = wn * 64 + nt * 8 + tig * 2;
            if (r0 < N_NODES)
                *(__half2*)(g_h16 + (size_t)r0 * D + col) =
                    __floats2half2_rn(c[mt][nt][0], c[mt][nt][1]);
            if (r0 + 8 < N_NODES)
                *(__half2*)(g_h16 + (size_t)(r0 + 8) * D + col) =
                    __floats2half2_rn(c[mt][nt][2], c[mt][nt][3]);
        }
    }
}

// ---------------- gather: AGG[dst] = prelu(h[dst]*dis^2 + sum h[src]*norm + b, a) --
__global__ void __launch_bounds__(256)
k_gather(int agg_sel, float* __restrict__ out_ext,
         const float* __restrict__ bias, const float* __restrict__ alpha, int n_off)
{
    int node = n_off + blockIdx.x * 8 + (threadIdx.x >> 5);
    if (node >= N_NODES) return;
    int lane = threadIdx.x & 31;

    float* AGG = (agg_sel == 1) ? g_x1 : out_ext;

    int start = g_rowstart[node];
    int end = start + g_cnt[node];
    float dn = g_dis[node];
    float sn = dn * dn;

    float4 hv = ld_h4(g_h16 + (size_t)node * D + lane * 4);
    float4 acc = make_float4(hv.x * sn, hv.y * sn, hv.z * sn, hv.w * sn);

    int j = start;
    for (; j + 3 < end; j += 4) {
        int2 e0 = g_edge[j],     e1 = g_edge[j + 1];
        int2 e2 = g_edge[j + 2], e3 = g_edge[j + 3];
        float4 h0 = ld_h4(g_h16 + (size_t)e0.x * D + lane * 4);
        float4 h1 = ld_h4(g_h16 + (size_t)e1.x * D + lane * 4);
        float4 h2 = ld_h4(g_h16 + (size_t)e2.x * D + lane * 4);
        float4 h3 = ld_h4(g_h16 + (size_t)e3.x * D + lane * 4);
        float v0 = __int_as_float(e0.y), v1 = __int_as_float(e1.y);
        float v2 = __int_as_float(e2.y), v3 = __int_as_float(e3.y);
        acc.x += h0.x * v0; acc.y += h0.y * v0; acc.z += h0.z * v0; acc.w += h0.w * v0;
        acc.x += h1.x * v1; acc.y += h1.y * v1; acc.z += h1.z * v1; acc.w += h1.w * v1;
        acc.x += h2.x * v2; acc.y += h2.y * v2; acc.z += h2.z * v2; acc.w += h2.w * v2;
        acc.x += h3.x * v3; acc.y += h3.y * v3; acc.z += h3.z * v3; acc.w += h3.w * v3;
    }
    for (; j < end; j++) {
        int2 e0 = g_edge[j];
        float v0 = __int_as_float(e0.y);
        float4 h0 = ld_h4(g_h16 + (size_t)e0.x * D + lane * 4);
        acc.x += h0.x * v0; acc.y += h0.y * v0; acc.z += h0.z * v0; acc.w += h0.w * v0;
    }

    if (bias) {
        int col = lane * 4;
        acc.x += bias[col + 0]; acc.x = acc.x >= 0.f ? acc.x : alpha[col + 0] * acc.x;
        acc.y += bias[col + 1]; acc.y = acc.y >= 0.f ? acc.y : alpha[col + 1] * acc.y;
        acc.z += bias[col + 2]; acc.z = acc.z >= 0.f ? acc.z : alpha[col + 2] * acc.z;
        acc.w += bias[col + 3]; acc.w = acc.w >= 0.f ? acc.w : alpha[col + 3] * acc.w;
    }
    *(float4*)(AGG + (size_t)node * D + lane * 4) = acc;
}

// ---------------- launch: gemm1 || CSR build ; gather1/gemm2 chunk pipeline -------
extern "C" void kernel_launch(void* const* d_in, const int* in_sizes, int n_in,
                              void* d_out, int out_size)
{
    const float* features = (const float*)d_in[0];
    const void*  ei       = d_in[1];
    const float* ew       = (const float*)d_in[2];
    const float* W1       = (const float*)d_in[3];
    const float* b1       = (const float*)d_in[4];
    const float* a1       = (const float*)d_in[5];
    const float* W2       = (const float*)d_in[6];
    const float* b2       = (const float*)d_in[7];
    const float* a2       = (const float*)d_in[8];
    float* out = (float*)d_out;

    const int nodeBlocks = (N_NODES + 255) / 256;            // 391
    const int edgeBlocks = (N_EDGES + 255) / 256;            // 6250
    const int gemmBlocks = (N_NODES + 127) / 128;            // 782
    const int gemmLo     = SPLIT_M / 128;                    // 391
    const int gemmHi     = gemmBlocks - gemmLo;              // 391
    const int gathLo     = SPLIT_M / 8;                      // 6256
    const int gathHi     = (N_NODES - SPLIT_M + 7) / 8;      // 6244
    const int gathBlocks = (N_NODES + 7) / 8;                // 12500

    cudaStream_t s2;
    cudaEvent_t ev_fork, e_g1, e_lo, e_hi, e_j;
    cudaStreamCreateWithFlags(&s2, cudaStreamNonBlocking);
    cudaEventCreateWithFlags(&ev_fork, cudaEventDisableTiming);
    cudaEventCreateWithFlags(&e_g1, cudaEventDisableTiming);
    cudaEventCreateWithFlags(&e_lo, cudaEventDisableTiming);
    cudaEventCreateWithFlags(&e_hi, cudaEventDisableTiming);
    cudaEventCreateWithFlags(&e_j, cudaEventDisableTiming);

    // fork: GEMM-1 (independent of CSR build) on s2
    cudaEventRecord(ev_fork, 0);
    cudaStreamWaitEvent(s2, ev_fork, 0);
    k_gemm<<<gemmBlocks, 256, 0, s2>>>(features, 0, W1, 0);
    cudaEventRecord(e_g1, s2);

    // main stream: prep + degree + scan + CSR fill
    k_prep<<<nodeBlocks, 256>>>((const int*)ei);
    k_deg_cnt<<<edgeBlocks, 256>>>(ei, ew);
    k_scan<<<N_SCAN_BLOCKS, SCAN_B>>>();
    k_fill<<<edgeBlocks, 256>>>(ei, ew);

    // join h16; gather-1 chunked, gemm-2 chunks pipelined on s2
    cudaStreamWaitEvent(0, e_g1, 0);
    k_gather<<<gathLo, 256>>>(1, out, b1, a1, 0);
    cudaEventRecord(e_lo, 0);
    k_gather<<<gathHi, 256>>>(1, out, b1, a1, SPLIT_M);
    cudaEventRecord(e_hi, 0);

    cudaStreamWaitEvent(s2, e_lo, 0);
    k_gemm<<<gemmLo, 256, 0, s2>>>(features, 1, W2, 0);
    cudaStreamWaitEvent(s2, e_hi, 0);
    k_gemm<<<gemmHi, 256, 0, s2>>>(features, 1, W2, SPLIT_M);
    cudaEventRecord(e_j, s2);

    cudaStreamWaitEvent(0, e_j, 0);
    k_gather<<<gathBlocks, 256>>>(2, out, b2, a2, 0);

    cudaEventDestroy(ev_fork);
    cudaEventDestroy(e_g1);
    cudaEventDestroy(e_lo);
    cudaEventDestroy(e_hi);
    cudaEventDestroy(e_j);
    cudaStreamDestroy(s2);
}

// round 16
// speedup vs baseline: 1.0943x; 1.0157x over previous
#include <cuda_runtime.h>
#include <cuda_fp16.h>
#include <cstdint>

#define N_NODES 100000
#define N_EDGES 1600000
#define D 128
#define SCAN_B 1024
#define N_SCAN_BLOCKS ((N_NODES + SCAN_B - 1) / SCAN_B)   // 98

// ---------------- scratch (device globals; no allocation allowed) ----------------
__device__ __align__(256) unsigned long long g_deg64[N_NODES]; // packed (cnt<<40 | wsum q20)
__device__ __align__(256) float  g_dis[N_NODES];              // rsqrt(deg)
__device__ __align__(256) int    g_cnt[N_NODES];              // in-degree (edges only)
__device__ __align__(256) int    g_rowstart[N_NODES];         // CSR row offsets
__device__ __align__(256) int    g_cursor[N_NODES];           // fill cursors (pre-offset)
__device__ __align__(256) int2   g_edge[N_EDGES];             // CSR (src, norm-bits)
__device__ __align__(256) __half g_h16[(size_t)N_NODES * D];  // GEMM output (fp16)
__device__ __align__(256) __half g_x1h[(size_t)N_NODES * D];  // layer-1 activated (fp16)
__device__ int g_idx64;                                       // edge_index dtype flag
__device__ int g_total;                                       // scan offset counter

// ---------------- helpers ----------------
__device__ __forceinline__ int clampN(int v) {
    v = v < 0 ? 0 : v;
    return v >= N_NODES ? N_NODES - 1 : v;
}

__device__ __forceinline__ int eidx(const void* ei, int is64, size_t pos) {
    if (is64) return clampN((int)((const long long*)ei)[pos]);
    return clampN(((const int*)ei)[pos]);
}

__device__ __forceinline__ uint32_t smem_u32(const void* p) {
    return (uint32_t)__cvta_generic_to_shared(p);
}

__device__ __forceinline__ void ldm_x4(uint32_t* r, uint32_t addr) {
    asm volatile("ldmatrix.sync.aligned.m8n8.x4.shared.b16 {%0,%1,%2,%3}, [%4];"
                 : "=r"(r[0]), "=r"(r[1]), "=r"(r[2]), "=r"(r[3]) : "r"(addr));
}

__device__ __forceinline__ void ldm_x4_t(uint32_t* r, uint32_t addr) {
    asm volatile("ldmatrix.sync.aligned.m8n8.x4.trans.shared.b16 {%0,%1,%2,%3}, [%4];"
                 : "=r"(r[0]), "=r"(r[1]), "=r"(r[2]), "=r"(r[3]) : "r"(addr));
}

__device__ __forceinline__ void mma_f16(float* c, const uint32_t* a, uint32_t b0, uint32_t b1) {
    asm volatile(
        "mma.sync.aligned.m16n8k16.row.col.f32.f16.f16.f32 "
        "{%0,%1,%2,%3}, {%4,%5,%6,%7}, {%8,%9}, {%0,%1,%2,%3};"
        : "+f"(c[0]), "+f"(c[1]), "+f"(c[2]), "+f"(c[3])
        : "r"(a[0]), "r"(a[1]), "r"(a[2]), "r"(a[3]), "r"(b0), "r"(b1));
}

__device__ __forceinline__ float4 ld_h4(const __half* p) {
    uint2 raw = *(const uint2*)p;
    __half2 p0 = *reinterpret_cast<__half2*>(&raw.x);
    __half2 p1 = *reinterpret_cast<__half2*>(&raw.y);
    float2 f0 = __half22float2(p0);
    float2 f1 = __half22float2(p1);
    return make_float4(f0.x, f0.y, f1.x, f1.y);
}

// ---------------- prep (+ dtype probe + scan counter reset) ----------------
__global__ void k_prep(const int* __restrict__ ei32) {
    int i = blockIdx.x * 256 + threadIdx.x;
    if (i < N_NODES) g_deg64[i] = 0ULL;
    if (i == 0) {
        g_total = 0;
        int odd_or = 0;
#pragma unroll
        for (int k = 1; k < 128; k += 2) odd_or |= ei32[k];
        g_idx64 = (odd_or == 0) ? 1 : 0;
    }
}

// ---------------- degree + count: ONE packed 64-bit atomic per edge ----------------
__global__ void k_deg_cnt(const void* __restrict__ ei, const float* __restrict__ w) {
    int e = blockIdx.x * 256 + threadIdx.x;
    if (e < N_EDGES) {
        int is64 = g_idx64;
        int d = eidx(ei, is64, (size_t)N_EDGES + e);
        unsigned int q = __float2uint_rn(w[e] * 1048576.0f);   // q20 fixed point
        atomicAdd(&g_deg64[d], (1ULL << 40) | (unsigned long long)q);
    }
}

// ---------------- single-kernel scan: local scan + atomic block base --------------
__global__ void k_scan() {
    __shared__ int sm[SCAN_B];
    __shared__ int base_sh;
    int tid = threadIdx.x;
    int i = blockIdx.x * SCAN_B + tid;
    int v = 0;
    if (i < N_NODES) {
        unsigned long long p = g_deg64[i];
        v = (int)(p >> 40);
        float wsum = (float)(p & ((1ULL << 40) - 1)) * (1.0f / 1048576.0f);
        g_dis[i] = rsqrtf(wsum + 1.0f);   // +1 self-loop
        g_cnt[i] = v;
    }
    sm[tid] = v;
    __syncthreads();
#pragma unroll
    for (int off = 1; off < SCAN_B; off <<= 1) {
        int t = (tid >= off) ? sm[tid - off] : 0;
        __syncthreads();
        sm[tid] += t;
        __syncthreads();
    }
    if (tid == SCAN_B - 1) base_sh = atomicAdd(&g_total, sm[tid]);
    __syncthreads();
    if (i < N_NODES) {
        int rs = base_sh + sm[tid] - v;
        g_rowstart[i] = rs;
        g_cursor[i] = rs;
    }
}

// ---------------- CSR fill: packed (src, norm) records ----------------
__global__ void k_fill(const void* __restrict__ ei, const float* __restrict__ w) {
    int e = blockIdx.x * 256 + threadIdx.x;
    if (e < N_EDGES) {
        int is64 = g_idx64;
        int s = eidx(ei, is64, e);
        int d = eidx(ei, is64, (size_t)N_EDGES + e);
        float nm = g_dis[s] * w[e] * g_dis[d];
        int pos = atomicAdd(&g_cursor[d], 1);
        pos = pos < 0 ? 0 : (pos >= N_EDGES ? N_EDGES - 1 : pos);
        g_edge[pos] = make_int2(s, __float_as_int(nm));
    }
}

// ---------------- FP16 tensor-core GEMM, double-buffered: H16 = A @ W ----------
// a_sel: 0 = Aext fp32 (features), 1 = g_x1h fp16 (already activated).
__global__ void __launch_bounds__(256, 2)
k_gemm(const float* __restrict__ Aext, int a_sel, const float* __restrict__ W)
{
    __shared__ __half As[2][128][24];   // [m][k], 24-half stride: ldmatrix conflict-free
    __shared__ __half Bs[2][16][136];   // [k][n], 136-half stride: ldmatrix conflict-free

    const int tid  = threadIdx.x;
    const int m0   = blockIdx.x * 128;
    const int wid  = tid >> 5, lane = tid & 31;
    const int wm   = wid >> 1, wn = wid & 1;      // warp grid 4x2
    const int gid  = lane >> 2, tig = lane & 3;   // mma accum coords
    const int li   = lane & 7,  lsel = lane >> 3; // ldmatrix coords

    float c[2][8][4];
#pragma unroll
    for (int mt = 0; mt < 2; mt++)
#pragma unroll
        for (int nt = 0; nt < 8; nt++)
#pragma unroll
            for (int q = 0; q < 4; q++) c[mt][nt][q] = 0.0f;

    float4 ra[2];       // fp32 A staging
    uint2  rah[2];      // fp16 A staging
    float4 rb[2];

    auto load_chunk = [&](int ch) {
#pragma unroll
        for (int it = 0; it < 2; it++) {
            int idx = tid + it * 256;
            int row = idx >> 2, c4 = idx & 3;
            int gm = m0 + row;
            if (a_sel == 0) {
                float4 v = make_float4(0.f, 0.f, 0.f, 0.f);
                if (gm < N_NODES)
                    v = *(const float4*)(Aext + (size_t)gm * D + ch * 16 + c4 * 4);
                ra[it] = v;
            } else {
                uint2 u = make_uint2(0u, 0u);
                if (gm < N_NODES)
                    u = *(const uint2*)(g_x1h + (size_t)gm * D + ch * 16 + c4 * 4);
                rah[it] = u;
            }
        }
#pragma unroll
        for (int it = 0; it < 2; it++) {
            int idx = tid + it * 256;
            int row = idx >> 5, c4 = idx & 31;
            rb[it] = *(const float4*)(W + (size_t)(ch * 16 + row) * D + c4 * 4);
        }
    };

    auto store_chunk = [&](int buf) {
#pragma unroll
        for (int it = 0; it < 2; it++) {
            int idx = tid + it * 256;
            int row = idx >> 2, c4 = idx & 3;
            uint2 u;
            if (a_sel == 0) {
                __half2 h01 = __floats2half2_rn(ra[it].x, ra[it].y);
                __half2 h23 = __floats2half2_rn(ra[it].z, ra[it].w);
                u = make_uint2(*(uint32_t*)&h01, *(uint32_t*)&h23);
            } else {
                u = rah[it];
            }
            *(uint2*)&As[buf][row][c4 * 4] = u;
        }
#pragma unroll
        for (int it = 0; it < 2; it++) {
            int idx = tid + it * 256;
            int row = idx >> 5, c4 = idx & 31;
            __half2 h01 = __floats2half2_rn(rb[it].x, rb[it].y);
            __half2 h23 = __floats2half2_rn(rb[it].z, rb[it].w);
            uint2 u = make_uint2(*(uint32_t*)&h01, *(uint32_t*)&h23);
            *(uint2*)&Bs[buf][row][c4 * 4] = u;
        }
    };

    load_chunk(0);
    store_chunk(0);
    __syncthreads();

    const int NCH = D / 16;  // 8
#pragma unroll
    for (int ch = 0; ch < NCH; ch++) {
        int buf = ch & 1;
        if (ch + 1 < NCH) load_chunk(ch + 1);

        uint32_t af[2][4];
#pragma unroll
        for (int mt = 0; mt < 2; mt++) {
            int row = wm * 32 + mt * 16 + (lsel & 1) * 8 + li;
            int col = (lsel >> 1) * 8;
            ldm_x4(af[mt], smem_u32(&As[buf][row][col]));
        }
        uint32_t bf[4][4];
#pragma unroll
        for (int np = 0; np < 4; np++) {
            int row = (lsel & 1) * 8 + li;
            int col = wn * 64 + np * 16 + (lsel >> 1) * 8;
            ldm_x4_t(bf[np], smem_u32(&Bs[buf][row][col]));
        }
#pragma unroll
        for (int mt = 0; mt < 2; mt++)
#pragma unroll
            for (int nt = 0; nt < 8; nt++)
                mma_f16(c[mt][nt], af[mt], bf[nt >> 1][(nt & 1) * 2], bf[nt >> 1][(nt & 1) * 2 + 1]);

        if (ch + 1 < NCH) {
            store_chunk(buf ^ 1);
            __syncthreads();
        }
    }

#pragma unroll
    for (int mt = 0; mt < 2; mt++) {
        int r0 = m0 + wm * 32 + mt * 16 + gid;
#pragma unroll
        for (int nt = 0; nt < 8; nt++) {
            int col = wn * 64 + nt * 8 + tig * 2;
            if (r0 < N_NODES)
                *(__half2*)(g_h16 + (size_t)r0 * D + col) =
                    __floats2half2_rn(c[mt][nt][0], c[mt][nt][1]);
            if (r0 + 8 < N_NODES)
                *(__half2*)(g_h16 + (size_t)(r0 + 8) * D + col) =
                    __floats2half2_rn(c[mt][nt][2], c[mt][nt][3]);
        }
    }
}

// ---------------- gather: AGG[dst] = prelu(h[dst]*dis^2 + sum h[src]*norm + b, a) --
// agg_sel == 1: write fp16 to g_x1h (same __floats2half2_rn gemm2 would apply).
// agg_sel == 2: write fp32 to out_ext.
__global__ void __launch_bounds__(256)
k_gather(int agg_sel, float* __restrict__ out_ext,
         const float* __restrict__ bias, const float* __restrict__ alpha)
{
    int node = blockIdx.x * 8 + (threadIdx.x >> 5);
    if (node >= N_NODES) return;
    int lane = threadIdx.x & 31;

    int start = g_rowstart[node];
    int end = start + g_cnt[node];
    float dn = g_dis[node];
    float sn = dn * dn;

    float4 hv = ld_h4(g_h16 + (size_t)node * D + lane * 4);
    float4 acc = make_float4(hv.x * sn, hv.y * sn, hv.z * sn, hv.w * sn);

    int j = start;
    for (; j + 3 < end; j += 4) {
        int2 e0 = g_edge[j],     e1 = g_edge[j + 1];
        int2 e2 = g_edge[j + 2], e3 = g_edge[j + 3];
        float4 h0 = ld_h4(g_h16 + (size_t)e0.x * D + lane * 4);
        float4 h1 = ld_h4(g_h16 + (size_t)e1.x * D + lane * 4);
        float4 h2 = ld_h4(g_h16 + (size_t)e2.x * D + lane * 4);
        float4 h3 = ld_h4(g_h16 + (size_t)e3.x * D + lane * 4);
        float v0 = __int_as_float(e0.y), v1 = __int_as_float(e1.y);
        float v2 = __int_as_float(e2.y), v3 = __int_as_float(e3.y);
        acc.x += h0.x * v0; acc.y += h0.y * v0; acc.z += h0.z * v0; acc.w += h0.w * v0;
        acc.x += h1.x * v1; acc.y += h1.y * v1; acc.z += h1.z * v1; acc.w += h1.w * v1;
        acc.x += h2.x * v2; acc.y += h2.y * v2; acc.z += h2.z * v2; acc.w += h2.w * v2;
        acc.x += h3.x * v3; acc.y += h3.y * v3; acc.z += h3.z * v3; acc.w += h3.w * v3;
    }
    for (; j < end; j++) {
        int2 e0 = g_edge[j];
        float v0 = __int_as_float(e0.y);
        float4 h0 = ld_h4(g_h16 + (size_t)e0.x * D + lane * 4);
        acc.x += h0.x * v0; acc.y += h0.y * v0; acc.z += h0.z * v0; acc.w += h0.w * v0;
    }

    int col = lane * 4;
    acc.x += bias[col + 0]; acc.x = acc.x >= 0.f ? acc.x : alpha[col + 0] * acc.x;
    acc.y += bias[col + 1]; acc.y = acc.y >= 0.f ? acc.y : alpha[col + 1] * acc.y;
    acc.z += bias[col + 2]; acc.z = acc.z >= 0.f ? acc.z : alpha[col + 2] * acc.z;
    acc.w += bias[col + 3]; acc.w = acc.w >= 0.f ? acc.w : alpha[col + 3] * acc.w;

    if (agg_sel == 1) {
        __half2 h01 = __floats2half2_rn(acc.x, acc.y);
        __half2 h23 = __floats2half2_rn(acc.z, acc.w);
        *(uint2*)(g_x1h + (size_t)node * D + col) =
            make_uint2(*(uint32_t*)&h01, *(uint32_t*)&h23);
    } else {
        *(float4*)(out_ext + (size_t)node * D + col) = acc;
    }
}

// ---------------- launch: gemm1 || CSR build ; serial gather1→gemm2→gather2 -------
extern "C" void kernel_launch(void* const* d_in, const int* in_sizes, int n_in,
                              void* d_out, int out_size)
{
    const float* features = (const float*)d_in[0];
    const void*  ei       = d_in[1];
    const float* ew       = (const float*)d_in[2];
    const float* W1       = (const float*)d_in[3];
    const float* b1       = (const float*)d_in[4];
    const float* a1       = (const float*)d_in[5];
    const float* W2       = (const float*)d_in[6];
    const float* b2       = (const float*)d_in[7];
    const float* a2       = (const float*)d_in[8];
    float* out = (float*)d_out;

    const int nodeBlocks = (N_NODES + 255) / 256;            // 391
    const int edgeBlocks = (N_EDGES + 255) / 256;            // 6250
    const int gemmBlocks = (N_NODES + 127) / 128;            // 782
    const int gathBlocks = (N_NODES + 7) / 8;                // 12500

    cudaStream_t s2;
    cudaEvent_t ev_fork, e_g1;
    cudaStreamCreateWithFlags(&s2, cudaStreamNonBlocking);
    cudaEventCreateWithFlags(&ev_fork, cudaEventDisableTiming);
    cudaEventCreateWithFlags(&e_g1, cudaEventDisableTiming);

    // fork: GEMM-1 (independent of CSR build) on s2
    cudaEventRecord(ev_fork, 0);
    cudaStreamWaitEvent(s2, ev_fork, 0);
    k_gemm<<<gemmBlocks, 256, 0, s2>>>(features, 0, W1);
    cudaEventRecord(e_g1, s2);

    // main stream: prep + degree + scan + CSR fill
    k_prep<<<nodeBlocks, 256>>>((const int*)ei);
    k_deg_cnt<<<edgeBlocks, 256>>>(ei, ew);
    k_scan<<<N_SCAN_BLOCKS, SCAN_B>>>();
    k_fill<<<edgeBlocks, 256>>>(ei, ew);

    // join h16; serial layer pipeline
    cudaStreamWaitEvent(0, e_g1, 0);
    k_gather<<<gathBlocks, 256>>>(1, out, b1, a1);
    k_gemm<<<gemmBlocks, 256>>>(features, 1, W2);
    k_gather<<<gathBlocks, 256>>>(2, out, b2, a2);

    cudaEventDestroy(ev_fork);
    cudaEventDestroy(e_g1);
    cudaStreamDestroy(s2);
}